// round 16
// baseline (speedup 1.0000x reference)
#include <cuda_runtime.h>
#include <cuda_bf16.h>
#include <cstdint>

// EdgeConv: B=16, N=8192, K=20, D=64
// Wc[o][d] = W[o][d] (o<64) ; W[o-64][64+d]-W[o-64][d] (o>=64)
// y[p][o]=x[p]·Wc[o] (o<64), z via o>=64.  out = gelu(LN(z + max_k y[ind]))
// k1 via mma.sync bf16 3-split. 2-half pipeline; k2(H0) on a LOW-PRIORITY
// side stream so k1(H1)'s 512 CTAs preempt k2's 8192-CTA backlog for slots.

#define B_  16
#define N_  8192
#define K_  20
#define P_  (B_ * N_)     // 131072
#define HALF_ (P_ / 2)    // 65536 = batches 0..7 / 8..15 (deps stay in-half)

__device__ float g_y[(size_t)P_ * 64];
__device__ float g_z[(size_t)P_ * 64];
__device__ unsigned short g_Wh[128 * 64];   // bf16 Wc hi, [o][d]
__device__ unsigned short g_Wl[128 * 64];   // bf16 Wc lo

__device__ __forceinline__ uint32_t smem_u32(const void* p) {
    uint32_t a;
    asm("{ .reg .u64 t; cvta.to.shared.u64 t, %1; cvt.u32.u64 %0, t; }"
        : "=r"(a) : "l"(p));
    return a;
}
#define SWZ(x) ((x) ^ (((x) >> 3) & 0x70))

#define LDSM_X4(r, a) \
    asm volatile("ldmatrix.sync.aligned.m8n8.x4.shared.b16 {%0,%1,%2,%3}, [%4];" \
        : "=r"((r)[0]), "=r"((r)[1]), "=r"((r)[2]), "=r"((r)[3]) : "r"(a))
#define LDSM_X2(r, a) \
    asm volatile("ldmatrix.sync.aligned.m8n8.x2.shared.b16 {%0,%1}, [%2];" \
        : "=r"((r)[0]), "=r"((r)[1]) : "r"(a))
#define MMA_BF16(c, a, b) \
    asm volatile("mma.sync.aligned.m16n8k16.row.col.f32.bf16.bf16.f32 " \
        "{%0,%1,%2,%3}, {%4,%5,%6,%7}, {%8,%9}, {%0,%1,%2,%3};" \
        : "+f"((c)[0]), "+f"((c)[1]), "+f"((c)[2]), "+f"((c)[3]) \
        : "r"((a)[0]), "r"((a)[1]), "r"((a)[2]), "r"((a)[3]), \
          "r"((b)[0]), "r"((b)[1]))

#define SM_AH 0
#define SM_AL 16384
#define SM_BH 32768
#define SM_BL 49152
#define SM_TOTAL 65536

// ---------------------------------------------------------------------------
__global__ void k_prep(const float* __restrict__ W)
{
    int idx = blockIdx.x * 256 + threadIdx.x;   // 0..8191
    int o = idx >> 6, d = idx & 63;
    float wc = (o < 64) ? W[o * 128 + d]
                        : W[(o - 64) * 128 + 64 + d] - W[(o - 64) * 128 + d];
    __nv_bfloat16 h = __float2bfloat16(wc);
    __nv_bfloat16 l = __float2bfloat16(wc - __bfloat162float(h));
    g_Wh[idx] = *(unsigned short*)&h;
    g_Wl[idx] = *(unsigned short*)&l;
}

// ---------------------------------------------------------------------------
// k1: CTA tile 128 pts x 128 outs, K=64. 8 warps, paired-nt, 80 regs (occ 3).
// ---------------------------------------------------------------------------
__global__ __launch_bounds__(256, 3)
void k1_hmma(const float* __restrict__ x, int poff)
{
    extern __shared__ char smem[];
    const uint32_t sb = smem_u32(smem);
    const int tid = threadIdx.x, wid = tid >> 5, lane = tid & 31;
    const size_t p0 = (size_t)poff + (size_t)blockIdx.x * 128;

#pragma unroll
    for (int i = 0; i < 4; i++) {
        int idx = i * 256 + tid;
        uint32_t off = SWZ((uint32_t)(idx * 16));
        *(uint4*)(smem + SM_BH + off) = ((const uint4*)g_Wh)[idx];
        *(uint4*)(smem + SM_BL + off) = ((const uint4*)g_Wl)[idx];
    }

    const float4* xb = (const float4*)(x + p0 * 64);
#pragma unroll
    for (int i = 0; i < 8; i++) {
        int idx = i * 256 + tid;
        int row = idx >> 4, c4 = idx & 15;
        float4 v = __ldg(xb + idx);
        float f[4] = { v.x, v.y, v.z, v.w };
        unsigned long long hv = 0ull, lv = 0ull;
#pragma unroll
        for (int e = 0; e < 4; e++) {
            __nv_bfloat16 h = __float2bfloat16(f[e]);
            __nv_bfloat16 l = __float2bfloat16(f[e] - __bfloat162float(h));
            hv |= (unsigned long long)(*(unsigned short*)&h) << (16 * e);
            lv |= (unsigned long long)(*(unsigned short*)&l) << (16 * e);
        }
        uint32_t off = SWZ((uint32_t)(row * 128 + c4 * 8));
        *(unsigned long long*)(smem + SM_AH + off) = hv;
        *(unsigned long long*)(smem + SM_AL + off) = lv;
    }
    __syncthreads();

    uint32_t ah[4][4], al[4][4];
    {
        int r  = wid * 16 + (lane & 15);
        int cb = (lane >> 4) * 16;
#pragma unroll
        for (int kt = 0; kt < 4; kt++) {
            uint32_t off = SWZ((uint32_t)(r * 128 + kt * 32 + cb));
            LDSM_X4(ah[kt], sb + SM_AH + off);
            LDSM_X4(al[kt], sb + SM_AL + off);
        }
    }

    const int brow = lane & 7;
    const int bkb  = ((lane >> 3) & 1) * 16;

#pragma unroll
    for (int np = 0; np < 8; np++) {
        int nt0 = np * 2, nt1 = np * 2 + 1;
        uint32_t bh0[4][2], bl0[4][2], bh1[4][2], bl1[4][2];
#pragma unroll
        for (int kt = 0; kt < 4; kt++) {
            uint32_t o0 = SWZ((uint32_t)((nt0 * 8 + brow) * 128 + kt * 32 + bkb));
            uint32_t o1 = SWZ((uint32_t)((nt1 * 8 + brow) * 128 + kt * 32 + bkb));
            LDSM_X2(bh0[kt], sb + SM_BH + o0);
            LDSM_X2(bl0[kt], sb + SM_BL + o0);
            LDSM_X2(bh1[kt], sb + SM_BH + o1);
            LDSM_X2(bl1[kt], sb + SM_BL + o1);
        }
        float c0[4] = {0.f, 0.f, 0.f, 0.f};
        float c1[4] = {0.f, 0.f, 0.f, 0.f};
#pragma unroll
        for (int kt = 0; kt < 4; kt++) {
            MMA_BF16(c0, ah[kt], bh0[kt]);
            MMA_BF16(c1, ah[kt], bh1[kt]);
            MMA_BF16(c0, ah[kt], bl0[kt]);
            MMA_BF16(c1, ah[kt], bl1[kt]);
            MMA_BF16(c0, al[kt], bh0[kt]);
            MMA_BF16(c1, al[kt], bh1[kt]);
        }
        size_t row = p0 + (size_t)wid * 16 + (lane >> 2);
        {
            float* gb = (nt0 < 8) ? g_y : g_z;
            int col = (nt0 & 7) * 8 + (lane & 3) * 2;
            *(float2*)(gb + row * 64 + col)       = make_float2(c0[0], c0[1]);
            *(float2*)(gb + (row + 8) * 64 + col) = make_float2(c0[2], c0[3]);
        }
        {
            float* gb = (nt1 < 8) ? g_y : g_z;
            int col = (nt1 & 7) * 8 + (lane & 3) * 2;
            *(float2*)(gb + row * 64 + col)       = make_float2(c1[0], c1[1]);
            *(float2*)(gb + (row + 8) * 64 + col) = make_float2(c1[2], c1[3]);
        }
    }
}

// ---------------------------------------------------------------------------
// k2 (R7 shape, best measured): warp per point.
// ---------------------------------------------------------------------------
__global__ __launch_bounds__(256)
void k2_gather(const int*   __restrict__ ind,
               const float* __restrict__ gamma,
               const float* __restrict__ beta,
               float*       __restrict__ out, int poff)
{
    int warp = threadIdx.x >> 5, lane = threadIdx.x & 31;
    size_t p = (size_t)poff + (size_t)blockIdx.x * 8 + warp;
    size_t bbase = (p >> 13) << 13;

    const int*  ip    = ind + p * K_;
    const char* ybase = (const char*)g_y + (bbase << 8) + lane * 8;

    float m0 = -3.402823466e+38f, m1 = -3.402823466e+38f;
#pragma unroll
    for (int k = 0; k < K_; k++) {
        int j = __ldg(ip + k);
        float2 yv = *(const float2*)(ybase + ((size_t)(unsigned)j << 8));
        m0 = fmaxf(m0, yv.x);
        m1 = fmaxf(m1, yv.y);
    }

    float2 zv = *(const float2*)(g_z + (p << 6) + lane * 2);
    float h0 = m0 + zv.x, h1 = m1 + zv.y;

    float s  = h0 + h1;
    float ss = h0 * h0 + h1 * h1;
#pragma unroll
    for (int o2 = 16; o2; o2 >>= 1) {
        s  += __shfl_xor_sync(0xffffffffu, s, o2);
        ss += __shfl_xor_sync(0xffffffffu, ss, o2);
    }
    float mu  = s * (1.0f / 64.0f);
    float var = fmaxf(ss * (1.0f / 64.0f) - mu * mu, 0.0f);
    float rs  = rsqrtf(var + 1e-5f);

    float2 g  = *(const float2*)(gamma + lane * 2);
    float2 be = *(const float2*)(beta  + lane * 2);
    float hn0 = (h0 - mu) * rs * g.x + be.x;
    float hn1 = (h1 - mu) * rs * g.y + be.y;

    float r0 = 0.5f * hn0 * (1.0f + erff(hn0 * 0.7071067811865475f));
    float r1 = 0.5f * hn1 * (1.0f + erff(hn1 * 0.7071067811865475f));

    *(float2*)(out + (p << 6) + lane * 2) = make_float2(r0, r1);
}

// ---------------------------------------------------------------------------
// Side stream at LEAST priority (numerically greatest) so the main stream's
// k1(H1) grid outranks k2(H0) for CTA dispatch. Created once at load.
// ---------------------------------------------------------------------------
namespace {
struct PipeCtx {
    cudaStream_t s2 = nullptr;
    cudaEvent_t  evA = nullptr, evB = nullptr;
    bool ok = false;
    PipeCtx() {
        int lo = 0, hi = 0;
        cudaDeviceGetStreamPriorityRange(&lo, &hi);   // lo = least priority
        ok = (cudaStreamCreateWithPriority(&s2, cudaStreamNonBlocking, lo) == cudaSuccess) &&
             (cudaEventCreateWithFlags(&evA, cudaEventDisableTiming) == cudaSuccess) &&
             (cudaEventCreateWithFlags(&evB, cudaEventDisableTiming) == cudaSuccess);
    }
};
PipeCtx g_pipe;
}

extern "C" void kernel_launch(void* const* d_in, const int* in_sizes, int n_in,
                              void* d_out, int out_size)
{
    const float* x     = (const float*)d_in[0];
    const int*   ind   = (const int*)  d_in[1];
    const float* W     = (const float*)d_in[2];
    const float* gamma = (const float*)d_in[3];
    const float* beta  = (const float*)d_in[4];
    float*       out   = (float*)d_out;

    cudaFuncSetAttribute(k1_hmma, cudaFuncAttributeMaxDynamicSharedMemorySize, SM_TOTAL);

    k_prep <<<32, 256>>>(W);
    k1_hmma<<<HALF_ / 128, 256, SM_TOTAL>>>(x, 0);

    if (g_pipe.ok) {
        // fork: k2(H0) on low-priority side stream; k1(H1) overlaps on main.
        cudaEventRecord(g_pipe.evA, 0);
        cudaStreamWaitEvent(g_pipe.s2, g_pipe.evA, 0);
        k2_gather<<<HALF_ / 8, 256, 0, g_pipe.s2>>>(ind, gamma, beta, out, 0);
        cudaEventRecord(g_pipe.evB, g_pipe.s2);

        k1_hmma<<<HALF_ / 128, 256, SM_TOTAL>>>(x, HALF_);

        // join, then tail half
        cudaStreamWaitEvent(0, g_pipe.evB, 0);
        k2_gather<<<HALF_ / 8, 256>>>(ind, gamma, beta, out, HALF_);
    } else {
        // sequential fallback (still correct)
        k2_gather<<<HALF_ / 8, 256>>>(ind, gamma, beta, out, 0);
        k1_hmma  <<<HALF_ / 128, 256, SM_TOTAL>>>(x, HALF_);
        k2_gather<<<HALF_ / 8, 256>>>(ind, gamma, beta, out, HALF_);
    }
}

// round 17
// speedup vs baseline: 1.0817x; 1.0817x over previous
#include <cuda_runtime.h>
#include <cuda_bf16.h>
#include <cstdint>

// EdgeConv: B=16, N=8192, K=20, D=64
// Wc[o][d] = W[o][d] (o<64) ; W[o-64][64+d]-W[o-64][d] (o>=64)
// y[p][o]=x[p]·Wc[o] (o<64), z via o>=64.  out = gelu(LN(z + max_k y[ind]))
// k1 via mma.sync bf16 3-split: x=xh+xl, Wc=Wh+Wl; y ~= xh*Wh + xh*Wl + xl*Wh.
// Flat sequential: prep + k1(R6 best: occ2/128regs) + k2(R7 best, LTS-capped).

#define B_  16
#define N_  8192
#define K_  20
#define P_  (B_ * N_)   // 131072

__device__ float g_y[(size_t)P_ * 64];
__device__ float g_z[(size_t)P_ * 64];
__device__ unsigned short g_Wh[128 * 64];   // bf16 Wc hi, [o][d], 128B rows
__device__ unsigned short g_Wl[128 * 64];   // bf16 Wc lo

__device__ __forceinline__ uint32_t smem_u32(const void* p) {
    uint32_t a;
    asm("{ .reg .u64 t; cvta.to.shared.u64 t, %1; cvt.u32.u64 %0, t; }"
        : "=r"(a) : "l"(p));
    return a;
}
#define SWZ(x) ((x) ^ (((x) >> 3) & 0x70))

#define LDSM_X4(r, a) \
    asm volatile("ldmatrix.sync.aligned.m8n8.x4.shared.b16 {%0,%1,%2,%3}, [%4];" \
        : "=r"((r)[0]), "=r"((r)[1]), "=r"((r)[2]), "=r"((r)[3]) : "r"(a))
#define LDSM_X2(r, a) \
    asm volatile("ldmatrix.sync.aligned.m8n8.x2.shared.b16 {%0,%1}, [%2];" \
        : "=r"((r)[0]), "=r"((r)[1]) : "r"(a))
#define MMA_BF16(c, a, b) \
    asm volatile("mma.sync.aligned.m16n8k16.row.col.f32.bf16.bf16.f32 " \
        "{%0,%1,%2,%3}, {%4,%5,%6,%7}, {%8,%9}, {%0,%1,%2,%3};" \
        : "+f"((c)[0]), "+f"((c)[1]), "+f"((c)[2]), "+f"((c)[3]) \
        : "r"((a)[0]), "r"((a)[1]), "r"((a)[2]), "r"((a)[3]), \
          "r"((b)[0]), "r"((b)[1]))

#define SM_AH 0
#define SM_AL 16384
#define SM_BH 32768
#define SM_BL 49152
#define SM_TOTAL 65536

// ---------------------------------------------------------------------------
// prep: Wc -> bf16 hi/lo split, [o][d], 128 rows x 64 cols
// ---------------------------------------------------------------------------
__global__ void k_prep(const float* __restrict__ W)
{
    int idx = blockIdx.x * 256 + threadIdx.x;   // 0..8191
    int o = idx >> 6, d = idx & 63;
    float wc = (o < 64) ? W[o * 128 + d]
                        : W[(o - 64) * 128 + 64 + d] - W[(o - 64) * 128 + d];
    __nv_bfloat16 h = __float2bfloat16(wc);
    __nv_bfloat16 l = __float2bfloat16(wc - __bfloat162float(h));
    g_Wh[idx] = *(unsigned short*)&h;
    g_Wl[idx] = *(unsigned short*)&l;
}

// ---------------------------------------------------------------------------
// k1 (R6 best-measured: 29.2us): CTA tile 128 pts x 128 outs, K=64, 8 warps,
// paired-nt mainloop, 2 CTAs/SM, 128 regs, no spills.
// ---------------------------------------------------------------------------
__global__ __launch_bounds__(256, 2)
void k1_hmma(const float* __restrict__ x)
{
    extern __shared__ char smem[];
    const uint32_t sb = smem_u32(smem);
    const int tid = threadIdx.x, wid = tid >> 5, lane = tid & 31;
    const size_t p0 = (size_t)blockIdx.x * 128;

    // --- stage B (Wh/Wl), SW128-swizzled 128B rows ---
#pragma unroll
    for (int i = 0; i < 4; i++) {
        int idx = i * 256 + tid;                     // uint4 units, 0..1023
        uint32_t off = SWZ((uint32_t)(idx * 16));
        *(uint4*)(smem + SM_BH + off) = ((const uint4*)g_Wh)[idx];
        *(uint4*)(smem + SM_BL + off) = ((const uint4*)g_Wl)[idx];
    }

    // --- stage A: x tile 128x64 f32 -> bf16 hi/lo, swizzled 8B stores ---
    const float4* xb = (const float4*)(x + p0 * 64);
#pragma unroll
    for (int i = 0; i < 8; i++) {
        int idx = i * 256 + tid;                     // float4 units, 0..2047
        int row = idx >> 4, c4 = idx & 15;
        float4 v = __ldg(xb + idx);
        float f[4] = { v.x, v.y, v.z, v.w };
        unsigned long long hv = 0ull, lv = 0ull;
#pragma unroll
        for (int e = 0; e < 4; e++) {
            __nv_bfloat16 h = __float2bfloat16(f[e]);
            __nv_bfloat16 l = __float2bfloat16(f[e] - __bfloat162float(h));
            hv |= (unsigned long long)(*(unsigned short*)&h) << (16 * e);
            lv |= (unsigned long long)(*(unsigned short*)&l) << (16 * e);
        }
        uint32_t off = SWZ((uint32_t)(row * 128 + c4 * 8));
        *(unsigned long long*)(smem + SM_AH + off) = hv;
        *(unsigned long long*)(smem + SM_AL + off) = lv;
    }
    __syncthreads();

    // --- A fragments: rows wid*16..+15, 4 k-tiles ---
    uint32_t ah[4][4], al[4][4];
    {
        int r  = wid * 16 + (lane & 15);
        int cb = (lane >> 4) * 16;
#pragma unroll
        for (int kt = 0; kt < 4; kt++) {
            uint32_t off = SWZ((uint32_t)(r * 128 + kt * 32 + cb));
            LDSM_X4(ah[kt], sb + SM_AH + off);
            LDSM_X4(al[kt], sb + SM_AL + off);
        }
    }

    const int brow = lane & 7;
    const int bkb  = ((lane >> 3) & 1) * 16;

#pragma unroll
    for (int np = 0; np < 8; np++) {
        int nt0 = np * 2, nt1 = np * 2 + 1;
        uint32_t bh0[4][2], bl0[4][2], bh1[4][2], bl1[4][2];
#pragma unroll
        for (int kt = 0; kt < 4; kt++) {
            uint32_t o0 = SWZ((uint32_t)((nt0 * 8 + brow) * 128 + kt * 32 + bkb));
            uint32_t o1 = SWZ((uint32_t)((nt1 * 8 + brow) * 128 + kt * 32 + bkb));
            LDSM_X2(bh0[kt], sb + SM_BH + o0);
            LDSM_X2(bl0[kt], sb + SM_BL + o0);
            LDSM_X2(bh1[kt], sb + SM_BH + o1);
            LDSM_X2(bl1[kt], sb + SM_BL + o1);
        }
        float c0[4] = {0.f, 0.f, 0.f, 0.f};
        float c1[4] = {0.f, 0.f, 0.f, 0.f};
#pragma unroll
        for (int kt = 0; kt < 4; kt++) {
            MMA_BF16(c0, ah[kt], bh0[kt]);
            MMA_BF16(c1, ah[kt], bh1[kt]);
            MMA_BF16(c0, ah[kt], bl0[kt]);
            MMA_BF16(c1, ah[kt], bl1[kt]);
            MMA_BF16(c0, al[kt], bh0[kt]);
            MMA_BF16(c1, al[kt], bh1[kt]);
        }
        size_t row = p0 + (size_t)wid * 16 + (lane >> 2);
        {
            float* gb = (nt0 < 8) ? g_y : g_z;
            int col = (nt0 & 7) * 8 + (lane & 3) * 2;
            *(float2*)(gb + row * 64 + col)       = make_float2(c0[0], c0[1]);
            *(float2*)(gb + (row + 8) * 64 + col) = make_float2(c0[2], c0[3]);
        }
        {
            float* gb = (nt1 < 8) ? g_y : g_z;
            int col = (nt1 & 7) * 8 + (lane & 3) * 2;
            *(float2*)(gb + row * 64 + col)       = make_float2(c1[0], c1[1]);
            *(float2*)(gb + (row + 8) * 64 + col) = make_float2(c1[2], c1[3]);
        }
    }
}

// ---------------------------------------------------------------------------
// k2 (R7 best-measured: 48.9us, at the LTS throughput cap): warp per point,
// lane owns dims (2*lane, 2*lane+1), 20 uniform __ldg index loads.
// ---------------------------------------------------------------------------
__global__ __launch_bounds__(256)
void k2_gather(const int*   __restrict__ ind,
               const float* __restrict__ gamma,
               const float* __restrict__ beta,
               float*       __restrict__ out)
{
    int warp = threadIdx.x >> 5, lane = threadIdx.x & 31;
    size_t p = (size_t)blockIdx.x * 8 + warp;
    size_t bbase = (p >> 13) << 13;   // b * N

    const int*  ip    = ind + p * K_;
    const char* ybase = (const char*)g_y + (bbase << 8) + lane * 8;

    float m0 = -3.402823466e+38f, m1 = -3.402823466e+38f;
#pragma unroll
    for (int k = 0; k < K_; k++) {
        int j = __ldg(ip + k);
        float2 yv = *(const float2*)(ybase + ((size_t)(unsigned)j << 8));
        m0 = fmaxf(m0, yv.x);
        m1 = fmaxf(m1, yv.y);
    }

    float2 zv = *(const float2*)(g_z + (p << 6) + lane * 2);
    float h0 = m0 + zv.x, h1 = m1 + zv.y;

    float s  = h0 + h1;
    float ss = h0 * h0 + h1 * h1;
#pragma unroll
    for (int o2 = 16; o2; o2 >>= 1) {
        s  += __shfl_xor_sync(0xffffffffu, s, o2);
        ss += __shfl_xor_sync(0xffffffffu, ss, o2);
    }
    float mu  = s * (1.0f / 64.0f);
    float var = fmaxf(ss * (1.0f / 64.0f) - mu * mu, 0.0f);
    float rs  = rsqrtf(var + 1e-5f);

    float2 g  = *(const float2*)(gamma + lane * 2);
    float2 be = *(const float2*)(beta  + lane * 2);
    float hn0 = (h0 - mu) * rs * g.x + be.x;
    float hn1 = (h1 - mu) * rs * g.y + be.y;

    float r0 = 0.5f * hn0 * (1.0f + erff(hn0 * 0.7071067811865475f));
    float r1 = 0.5f * hn1 * (1.0f + erff(hn1 * 0.7071067811865475f));

    *(float2*)(out + (p << 6) + lane * 2) = make_float2(r0, r1);
}

// ---------------------------------------------------------------------------
extern "C" void kernel_launch(void* const* d_in, const int* in_sizes, int n_in,
                              void* d_out, int out_size)
{
    const float* x     = (const float*)d_in[0];
    const int*   ind   = (const int*)  d_in[1];
    const float* W     = (const float*)d_in[2];
    const float* gamma = (const float*)d_in[3];
    const float* beta  = (const float*)d_in[4];
    float*       out   = (float*)d_out;

    cudaFuncSetAttribute(k1_hmma, cudaFuncAttributeMaxDynamicSharedMemorySize, SM_TOTAL);

    k_prep   <<<32, 256>>>(W);
    k1_hmma  <<<P_ / 128, 256, SM_TOTAL>>>(x);
    k2_gather<<<P_ / 8, 256>>>(ind, gamma, beta, out);
}